// round 1
// baseline (speedup 1.0000x reference)
#include <cuda_runtime.h>

// 8x8 IDCT, separable form:
//   out = 0.25 * M'^T * S * M' + 128,  M'[y][v] = a[y]*cos((2v+1)*y*pi/16)
// One thread per 8x8-block ROW. Warp = 4 blocks (4 groups of 8 lanes).
// Row pass in registers -> 8x8 register transpose via shfl.bfly within the
// 8-lane group -> column pass -> transpose back -> coalesced 128-bit store.

#define FULLMASK 0xFFFFFFFFu

__device__ __forceinline__ void transpose8(float v[8], int r) {
    // 8x8 transpose distributed one-row-per-lane across an 8-lane group.
    // r = lane & 7. Three xor-butterfly stages; all reg indices compile-time.
#pragma unroll
    for (int m = 1; m < 8; m <<= 1) {
#pragma unroll
        for (int i = 0; i < 8; i++) {
            if (i & m) continue;
            const int j = i | m;
            const bool up = (r & m) != 0;
            float send = up ? v[i] : v[j];
            float recv = __shfl_xor_sync(FULLMASK, send, m);
            if (up) v[i] = recv; else v[j] = recv;
        }
    }
}

__global__ void __launch_bounds__(256)
idct_54271206752953_kernel(const float* __restrict__ in,
                           float* __restrict__ out,
                           int n_rows) {
    // M[y][v] = a[y] * cos((2v+1)*y*pi/16); a[0]=1/sqrt(2), a[y>0]=1.
    // Compile-time constants -> FFMA with immediate multiplier (no loads).
    const float M[8][8] = {
        { 0.70710678f,  0.70710678f,  0.70710678f,  0.70710678f,
          0.70710678f,  0.70710678f,  0.70710678f,  0.70710678f },
        { 0.98078528f,  0.83146961f,  0.55557023f,  0.19509032f,
         -0.19509032f, -0.55557023f, -0.83146961f, -0.98078528f },
        { 0.92387953f,  0.38268343f, -0.38268343f, -0.92387953f,
         -0.92387953f, -0.38268343f,  0.38268343f,  0.92387953f },
        { 0.83146961f, -0.19509032f, -0.98078528f, -0.55557023f,
          0.55557023f,  0.98078528f,  0.19509032f, -0.83146961f },
        { 0.70710678f, -0.70710678f, -0.70710678f,  0.70710678f,
          0.70710678f, -0.70710678f, -0.70710678f,  0.70710678f },
        { 0.55557023f, -0.98078528f,  0.19509032f,  0.83146961f,
         -0.83146961f, -0.19509032f,  0.98078528f, -0.55557023f },
        { 0.38268343f, -0.92387953f,  0.92387953f, -0.38268343f,
         -0.38268343f,  0.92387953f, -0.92387953f,  0.38268343f },
        { 0.19509032f, -0.55557023f,  0.83146961f, -0.98078528f,
          0.98078528f, -0.83146961f,  0.55557023f, -0.19509032f },
    };

    const int t = blockIdx.x * blockDim.x + threadIdx.x;
    if (t >= n_rows) return;
    const int r = threadIdx.x & 7;  // row index within the 8x8 block

    // Load this thread's row: 8 consecutive floats = 2 x float4.
    const float4* in4 = reinterpret_cast<const float4*>(in) + (size_t)t * 2;
    float4 lo = in4[0];
    float4 hi = in4[1];
    float s[8] = { lo.x, lo.y, lo.z, lo.w, hi.x, hi.y, hi.z, hi.w };

    // Row pass: a[v] = sum_y s[y] * M[y][v]
    float acc[8];
#pragma unroll
    for (int v = 0; v < 8; v++) {
        float a = s[0] * M[0][v];
#pragma unroll
        for (int y = 1; y < 8; y++) a = fmaf(s[y], M[y][v], a);
        acc[v] = a;
    }

    // Transpose: lane p now holds column v=p, values over x in acc[x].
    transpose8(acc, r);

    // Column pass: o[u] = sum_x acc[x] * M[x][u], then scale+bias.
    float o[8];
#pragma unroll
    for (int u = 0; u < 8; u++) {
        float a = acc[0] * M[0][u];
#pragma unroll
        for (int x = 1; x < 8; x++) a = fmaf(acc[x], M[x][u], a);
        o[u] = fmaf(a, 0.25f, 128.0f);
    }

    // Transpose back: lane r holds output row u=r, values over v.
    transpose8(o, r);

    // Coalesced 128-bit store of this thread's output row.
    float4* out4 = reinterpret_cast<float4*>(out) + (size_t)t * 2;
    out4[0] = make_float4(o[0], o[1], o[2], o[3]);
    out4[1] = make_float4(o[4], o[5], o[6], o[7]);
}

extern "C" void kernel_launch(void* const* d_in, const int* in_sizes, int n_in,
                              void* d_out, int out_size) {
    const float* images = (const float*)d_in[0];
    float* out = (float*)d_out;
    // in_sizes[0] = B*N*64 floats; one thread per 8-float row.
    const int n_rows = in_sizes[0] / 8;
    const int threads = 256;
    const int blocks = (n_rows + threads - 1) / threads;
    idct_54271206752953_kernel<<<blocks, threads>>>(images, out, n_rows);
}

// round 2
// speedup vs baseline: 1.0299x; 1.0299x over previous
#include <cuda_runtime.h>

// 8x8 IDCT, separable + even/odd symmetry:
//   out = 0.25 * M^T * S * M + 128,  M[y][v] = a[y]*cos((2v+1)*y*pi/16)
// Symmetry: M[y][7-v] = (-1)^y * M[y][v]  ->  each 1D pass = 4 even-sums +
// 4 odd-sums + 4 add/sub pairs (40 ops instead of 64).
// One thread per 8x8-block ROW (8 lanes = 1 block). Row pass in registers ->
// one 8x8 register transpose (shfl.bfly) -> column pass (0.25 folded into
// constants, +128 folded into accumulator init) -> direct scalar stores
// (lane p holds output column p; no second transpose needed).

#define FULLMASK 0xFFFFFFFFu

__device__ __forceinline__ void transpose8(float v[8], int r) {
#pragma unroll
    for (int m = 1; m < 8; m <<= 1) {
#pragma unroll
        for (int i = 0; i < 8; i++) {
            if (i & m) continue;
            const int j = i | m;
            const bool up = (r & m) != 0;
            float send = up ? v[i] : v[j];
            float recv = __shfl_xor_sync(FULLMASK, send, m);
            if (up) v[i] = recv; else v[j] = recv;
        }
    }
}

__global__ void __launch_bounds__(256)
idct_54271206752953_kernel(const float* __restrict__ in,
                           float* __restrict__ out,
                           int n_rows) {
    // Even rows of M (y = 0,2,4,6), columns v = 0..3:
    const float ME[4][4] = {
        { 0.70710678f,  0.70710678f,  0.70710678f,  0.70710678f },  // y=0
        { 0.92387953f,  0.38268343f, -0.38268343f, -0.92387953f },  // y=2
        { 0.70710678f, -0.70710678f, -0.70710678f,  0.70710678f },  // y=4
        { 0.38268343f, -0.92387953f,  0.92387953f, -0.38268343f },  // y=6
    };
    // Odd rows of M (y = 1,3,5,7), columns v = 0..3:
    const float MO[4][4] = {
        { 0.98078528f,  0.83146961f,  0.55557023f,  0.19509032f },  // y=1
        { 0.83146961f, -0.19509032f, -0.98078528f, -0.55557023f },  // y=3
        { 0.55557023f, -0.98078528f,  0.19509032f,  0.83146961f },  // y=5
        { 0.19509032f, -0.55557023f,  0.83146961f, -0.98078528f },  // y=7
    };

    const int t = blockIdx.x * blockDim.x + threadIdx.x;
    if (t >= n_rows) return;
    const int r = threadIdx.x & 7;  // row index within the 8x8 block

    // Load this thread's row: 8 consecutive floats = 2 x LDG.128.
    const float4* in4 = reinterpret_cast<const float4*>(in) + (size_t)t * 2;
    float4 lo = in4[0];
    float4 hi = in4[1];
    float s[8] = { lo.x, lo.y, lo.z, lo.w, hi.x, hi.y, hi.z, hi.w };

    // Row pass: acc[v] = sum_y s[y]*M[y][v], via even/odd split.
    float acc[8];
#pragma unroll
    for (int v = 0; v < 4; v++) {
        float e = s[0] * ME[0][v];
        e = fmaf(s[2], ME[1][v], e);
        e = fmaf(s[4], ME[2][v], e);
        e = fmaf(s[6], ME[3][v], e);
        float o = s[1] * MO[0][v];
        o = fmaf(s[3], MO[1][v], o);
        o = fmaf(s[5], MO[2][v], o);
        o = fmaf(s[7], MO[3][v], o);
        acc[v]     = e + o;
        acc[7 - v] = e - o;
    }

    // Transpose: lane p now holds intermediate column p (values over x).
    transpose8(acc, r);

    // Column pass: out[u] = 0.25 * sum_x acc[x]*M[x][u] + 128.
    // 0.25 folded into constants, +128 folded into even-accumulator init.
    float o[8];
#pragma unroll
    for (int u = 0; u < 4; u++) {
        float e = fmaf(acc[0], 0.25f * ME[0][u], 128.0f);
        e = fmaf(acc[2], 0.25f * ME[1][u], e);
        e = fmaf(acc[4], 0.25f * ME[2][u], e);
        e = fmaf(acc[6], 0.25f * ME[3][u], e);
        float od = acc[1] * (0.25f * MO[0][u]);
        od = fmaf(acc[3], 0.25f * MO[1][u], od);
        od = fmaf(acc[5], 0.25f * MO[2][u], od);
        od = fmaf(acc[7], 0.25f * MO[3][u], od);
        o[u]     = e + od;
        o[7 - u] = e - od;
    }

    // Lane p holds output COLUMN p: out[block*64 + u*8 + p], u = 0..7.
    // Warp-level each scalar store covers complete 32B sectors (8 contiguous
    // lanes x 4 blocks), so no second transpose is needed.
    float* op = out + ((size_t)(t >> 3)) * 64 + r;
#pragma unroll
    for (int u = 0; u < 8; u++) op[u * 8] = o[u];
}

extern "C" void kernel_launch(void* const* d_in, const int* in_sizes, int n_in,
                              void* d_out, int out_size) {
    const float* images = (const float*)d_in[0];
    float* out = (float*)d_out;
    const int n_rows = in_sizes[0] / 8;  // one thread per 8-float row
    const int threads = 256;
    const int blocks = (n_rows + threads - 1) / threads;
    idct_54271206752953_kernel<<<blocks, threads>>>(images, out, n_rows);
}